// round 11
// baseline (speedup 1.0000x reference)
#include <cuda_runtime.h>
#include <cuda_fp16.h>
#include <mma.h>

using namespace nvcuda;

// Problem constants (GCN_48473000903499): N=50000, D=64, L=3, OUT=16, E=800000
#define NN   50000
#define DD   64
#define OUTK 16
#define EE   800000
#define NE   (EE + NN)            // edges + self loops = 850000
#define NEP  (NE + 7 * NN)        // CSR capacity with per-row pad-to-8
#define NM   (NN * DD)            // 3,200,000 flat elements
#define NH2  (NN * 32)            // half2 count of real rows
#define NH2P ((NN + 1) * 32)      // + one zero pad row (index NN)
#define LDS_PAD 72                // smem row stride (halves / floats)

// ---- scratch (device globals; no allocation allowed) ----
// g_ints: [0,NN) deg_out(edges), [NN,2NN) deg_in(edges)->padded row len, [2NN] alloc counter
__device__ int     g_ints[2 * NN + 1];
__device__ int     g_off[NN];
__device__ int     g_cursor[NN];
__device__ int     g_csr_src[NEP];
__device__ float   g_norm_src[NN];
__device__ float   g_norm_dst[NN];
__device__ __align__(16) __half2 g_ha[NH2P];   // fp16 feature ping (row NN = zeros)
__device__ __align__(16) __half2 g_hb[NH2P];   // fp16 feature pong (row NN = zeros)
__device__ __align__(16) __half  g_wh[3 * DD * DD];  // fp16-converted gcn_w
__device__ float   g_xf[NM];       // final-layer fp32 output (FC input)

__device__ __forceinline__ float2 h2f_bits(float w) {
    unsigned u = __float_as_uint(w);
    __half2 h = *reinterpret_cast<__half2*>(&u);
    return __half22float2(h);
}

// ---------------------------------------------------------------------------
// 1. histogram edges (deg arrays pre-zeroed by memset)
__global__ void k_hist(const int* __restrict__ src, const int* __restrict__ dst) {
    int e = blockIdx.x * blockDim.x + threadIdx.x;
    if (e < EE) {
        atomicAdd(&g_ints[src[e]], 1);          // deg_out
        atomicAdd(&g_ints[NN + dst[e]], 1);     // deg_in
    }
}

// 2. per-node: norms (+1 self loop), padded CSR slot alloc, pad-fill with zero-row
//    index NN, bias init, zero pad feature rows, and fp16-convert gcn_w (once).
__global__ void k_build(const float* __restrict__ fc_b, float* __restrict__ out,
                        const float* __restrict__ gcn_w) {
    int i = blockIdx.x * blockDim.x + threadIdx.x;
    if (i < NN) {
        int dout = g_ints[i] + 1;
        int din  = g_ints[NN + i] + 1;          // entries incl. self loop
        g_norm_src[i] = rsqrtf((float)dout);
        g_norm_dst[i] = rsqrtf((float)din);
        int dpad = (din + 7) & ~7;
        int off = atomicAdd(&g_ints[2 * NN], dpad);
        g_off[i] = off;
        g_cursor[i] = off;
        g_ints[NN + i] = dpad;                  // repurpose: padded row length
        for (int p = off + din; p < off + dpad; p++) g_csr_src[p] = NN;
    }
    if (blockIdx.x == 0) {
        if (threadIdx.x < OUTK) out[threadIdx.x] = fc_b[threadIdx.x];
        if (threadIdx.x >= 32 && threadIdx.x < 64) {   // zero pad rows
            int l = threadIdx.x - 32;
            g_ha[NN * 32 + l] = __floats2half2_rn(0.f, 0.f);
            g_hb[NN * 32 + l] = __floats2half2_rn(0.f, 0.f);
        }
    }
    // blocks 100..147: convert 3*64*64 = 12288 W entries to fp16
    if (blockIdx.x >= 100 && blockIdx.x < 148) {
        int wi = (blockIdx.x - 100) * 256 + threadIdx.x;
        g_wh[wi] = __float2half(gcn_w[wi]);
    }
}

// 3. fused: scatter edges+loops into CSR, and premul F*norm_src -> fp16 ha
__global__ void k_scatpre(const int* __restrict__ src, const int* __restrict__ dst,
                          const float* __restrict__ F) {
    int i = blockIdx.x * blockDim.x + threadIdx.x;
    if (i < NE) {
        if (i < EE) {
            int d = dst[i];
            int p = atomicAdd(&g_cursor[d], 1);
            g_csr_src[p] = src[i];
        } else {
            int n = i - EE;
            int p = atomicAdd(&g_cursor[n], 1);
            g_csr_src[p] = n;
        }
    } else {
        int j = i - NE;                         // half2 index
        if (j < NH2) {
            float2 f = ((const float2*)F)[j];
            float ns = g_norm_src[j >> 5];
            g_ha[j] = __floats2half2_rn(f.x * ns, f.y * ns);
        }
    }
}

// 4. fused SpMM gather + HMMA GEMM + bias + relu. 64 nodes per block, 8 warps.
//    Gather: 4 source rows per LDG.128; rolling v[4] double-buffer keeps 4
//    LDG.128 in flight with only 16 regs of staging -> 5 blocks/SM residency.
struct SmemP1 { __half Wh[DD][LDS_PAD]; __half aggh[DD][LDS_PAD]; };
union  SmemU  { SmemP1 p1; float outS[DD][LDS_PAD]; };

template <bool HALF_OUT>
__global__ void __launch_bounds__(256, 5) k_layer(
    const __half2* __restrict__ x2, const __half* __restrict__ Wh16,
    const float* __restrict__ b, __half2* __restrict__ yh, float* __restrict__ yf)
{
    __shared__ SmemU sm;
    __shared__ float bsh[DD];

    int tid = threadIdx.x;
    int warp = tid >> 5, lane = tid & 31;
    int nodeBase = blockIdx.x * 64;

    // W tile: fp16 copy, vectorized uint2 (8B) to respect 144B row stride
    {
        const uint2* ws = (const uint2*)Wh16;
        for (int i = tid; i < DD * DD / 4; i += 256) {
            uint2 u = ws[i];
            *(uint2*)&sm.p1.Wh[i >> 4][(i * 4) & 63] = u;
        }
    }
    if (tid < DD) bsh[tid] = b[tid];

    // lane-parallel preload: lanes 0-7 offsets, 8-15 padded lens, 16-23 dst-norms
    int group = nodeBase + warp * 8;
    int offv = 0, lenv = 0; float ndv = 0.f;
    if (lane < 8 && group + lane < NN)
        offv = g_off[group + lane];
    if (lane >= 8 && lane < 16 && group + lane - 8 < NN)
        lenv = g_ints[NN + group + lane - 8];
    if (lane >= 16 && lane < 24 && group + lane - 16 < NN)
        ndv = g_norm_dst[group + lane - 16];
    __syncthreads();

    // ---- Phase A: gather (4 rows per LDG.128, rolling 4-deep pipeline) ----
    const float4* xr = (const float4*)x2;      // row = 8 float4s (128 B)
    int rowgrp = lane >> 3;                    // 0..3
    int chunk  = lane & 7;                     // 16B column chunk
    #pragma unroll 1
    for (int it = 0; it < 8; it++) {
        int s0  = __shfl_sync(0xffffffffu, offv, it);
        int len = __shfl_sync(0xffffffffu, lenv, 8 + it);  // multiple of 8 (0 if OOB)
        float2 a0 = {0.f, 0.f}, a1 = {0.f, 0.f}, a2 = {0.f, 0.f}, a3 = {0.f, 0.f};

        #pragma unroll 1
        for (int base = 0; base < len; base += 32) {
            int rem = len - base;
            int s = (lane < rem) ? g_csr_src[s0 + base + lane] : NN;
            int nb = (rem < 32 ? rem : 32) >> 2;        // 2,4,6,8 batches of 4 rows
            float4 v[4];
            #pragma unroll
            for (int q = 0; q < 4; q++) {
                if (q < nb) {
                    int ss = __shfl_sync(0xffffffffu, s, q * 4 + rowgrp);
                    v[q] = __ldg(&xr[ss * 8 + chunk]);
                }
            }
            #pragma unroll
            for (int q = 0; q < 8; q++) {
                if (q < nb) {
                    float4 f = v[q & 3];
                    if (q + 4 < nb) {
                        int ss = __shfl_sync(0xffffffffu, s, (q + 4) * 4 + rowgrp);
                        v[q & 3] = __ldg(&xr[ss * 8 + chunk]);
                    }
                    float2 f0 = h2f_bits(f.x), f1 = h2f_bits(f.y);
                    float2 f2 = h2f_bits(f.z), f3 = h2f_bits(f.w);
                    a0.x += f0.x; a0.y += f0.y;
                    a1.x += f1.x; a1.y += f1.y;
                    a2.x += f2.x; a2.y += f2.y;
                    a3.x += f3.x; a3.y += f3.y;
                }
            }
        }
        // fold the 4 row-group partials (lanes c, c+8, c+16, c+24)
        #pragma unroll
        for (int st = 16; st >= 8; st >>= 1) {
            a0.x += __shfl_xor_sync(0xffffffffu, a0.x, st);
            a0.y += __shfl_xor_sync(0xffffffffu, a0.y, st);
            a1.x += __shfl_xor_sync(0xffffffffu, a1.x, st);
            a1.y += __shfl_xor_sync(0xffffffffu, a1.y, st);
            a2.x += __shfl_xor_sync(0xffffffffu, a2.x, st);
            a2.y += __shfl_xor_sync(0xffffffffu, a2.y, st);
            a3.x += __shfl_xor_sync(0xffffffffu, a3.x, st);
            a3.y += __shfl_xor_sync(0xffffffffu, a3.y, st);
        }
        float nd = __shfl_sync(0xffffffffu, ndv, 16 + it);
        if (rowgrp == 0) {
            int local = warp * 8 + it;
            __half2* dp = (__half2*)&sm.p1.aggh[local][chunk * 8];
            dp[0] = __floats2half2_rn(a0.x * nd, a0.y * nd);
            dp[1] = __floats2half2_rn(a1.x * nd, a1.y * nd);
            dp[2] = __floats2half2_rn(a2.x * nd, a2.y * nd);
            dp[3] = __floats2half2_rn(a3.x * nd, a3.y * nd);
        }
    }
    __syncthreads();

    // ---- Phase B: 64x64x64 GEMM via HMMA (C kept in regs across barrier) ----
    int mi = warp >> 1;                // m-strip 0..3 (16 rows each)
    int n0 = (warp & 1) * 2;           // n-tile pair: tiles n0, n0+1

    wmma::fragment<wmma::accumulator, 16, 16, 16, float> cF0, cF1;
    wmma::fill_fragment(cF0, 0.f);
    wmma::fill_fragment(cF1, 0.f);
    #pragma unroll
    for (int k = 0; k < 4; k++) {
        wmma::fragment<wmma::matrix_a, 16, 16, 16, __half, wmma::row_major> aF;
        wmma::load_matrix_sync(aF, &sm.p1.aggh[mi * 16][k * 16], LDS_PAD);
        wmma::fragment<wmma::matrix_b, 16, 16, 16, __half, wmma::row_major> bF;
        wmma::load_matrix_sync(bF, &sm.p1.Wh[k * 16][n0 * 16], LDS_PAD);
        wmma::mma_sync(cF0, aF, bF, cF0);
        wmma::load_matrix_sync(bF, &sm.p1.Wh[k * 16][(n0 + 1) * 16], LDS_PAD);
        wmma::mma_sync(cF1, aF, bF, cF1);
    }
    __syncthreads();    // everyone done reading Wh/aggh; smem now becomes outS
    wmma::store_matrix_sync(&sm.outS[mi * 16][n0 * 16], cF0, LDS_PAD,
                            wmma::mem_row_major);
    wmma::store_matrix_sync(&sm.outS[mi * 16][(n0 + 1) * 16], cF1, LDS_PAD,
                            wmma::mem_row_major);
    __syncthreads();

    // ---- Phase C: epilogue ----
    int c0 = lane * 2;
    #pragma unroll 1
    for (int r = warp * 8; r < warp * 8 + 8; r++) {
        int node = nodeBase + r;
        if (node >= NN) break;
        float o0 = fmaxf(sm.outS[r][c0]     + bsh[c0],     0.f);
        float o1 = fmaxf(sm.outS[r][c0 + 1] + bsh[c0 + 1], 0.f);
        if (HALF_OUT) {
            float ns = g_norm_src[node];
            yh[node * 32 + lane] = __floats2half2_rn(o0 * ns, o1 * ns);
        } else {
            *(float2*)&yf[node * DD + c0] = make_float2(o0, o1);
        }
    }
}

// 5. out += fc_w @ relu(flat)   (DRAM-streaming GEMV; fc_w streamed evict-first)
__global__ void __launch_bounds__(256) k_fc(
    const float* __restrict__ fc_w, const float* __restrict__ xflat,
    float* __restrict__ out)
{
    __shared__ float sh[OUTK];
    if (threadIdx.x < OUTK) sh[threadIdx.x] = 0.f;
    __syncthreads();

    const int nv = NM / 4;  // 800000 float4s per output row
    float acc[OUTK];
    #pragma unroll
    for (int o = 0; o < OUTK; o++) acc[o] = 0.f;

    const float4* w4 = (const float4*)fc_w;
    const float4* x4 = (const float4*)xflat;
    int stride = gridDim.x * blockDim.x;
    for (int i = blockIdx.x * blockDim.x + threadIdx.x; i < nv; i += stride) {
        float4 f = x4[i];
        f.x = fmaxf(f.x, 0.f); f.y = fmaxf(f.y, 0.f);
        f.z = fmaxf(f.z, 0.f); f.w = fmaxf(f.w, 0.f);
        #pragma unroll
        for (int o = 0; o < OUTK; o++) {
            float4 w = __ldcs(&w4[(size_t)o * nv + i]);
            acc[o] = fmaf(w.x, f.x, acc[o]);
            acc[o] = fmaf(w.y, f.y, acc[o]);
            acc[o] = fmaf(w.z, f.z, acc[o]);
            acc[o] = fmaf(w.w, f.w, acc[o]);
        }
    }

    #pragma unroll
    for (int o = 0; o < OUTK; o++) {
        float v = acc[o];
        #pragma unroll
        for (int s = 16; s; s >>= 1) v += __shfl_xor_sync(0xffffffffu, v, s);
        if ((threadIdx.x & 31) == 0) atomicAdd(&sh[o], v);
    }
    __syncthreads();
    if (threadIdx.x < OUTK) atomicAdd(&out[threadIdx.x], sh[threadIdx.x]);
}

// ---------------------------------------------------------------------------
extern "C" void kernel_launch(void* const* d_in, const int* in_sizes, int n_in,
                              void* d_out, int out_size)
{
    const float* F     = (const float*)d_in[0];
    const int*   src   = (const int*)d_in[1];
    const int*   dst   = (const int*)d_in[2];
    const float* gcn_w = (const float*)d_in[3];
    const float* gcn_b = (const float*)d_in[4];
    const float* fc_w  = (const float*)d_in[5];
    const float* fc_b  = (const float*)d_in[6];
    float* out = (float*)d_out;

    void* ints_addr;   cudaGetSymbolAddress(&ints_addr, g_ints);
    __half2* ha; cudaGetSymbolAddress((void**)&ha, g_ha);
    __half2* hb; cudaGetSymbolAddress((void**)&hb, g_hb);
    __half*  wh; cudaGetSymbolAddress((void**)&wh, g_wh);
    float*   xf; cudaGetSymbolAddress((void**)&xf, g_xf);

    // graph prep
    cudaMemsetAsync(ints_addr, 0, (2 * NN + 1) * sizeof(int));
    k_hist<<<(EE + 255) / 256, 256>>>(src, dst);
    k_build<<<(NN + 255) / 256, 256>>>(fc_b, out, gcn_w);
    k_scatpre<<<(NE + NH2 + 255) / 256, 256>>>(src, dst, F);

    // 3 GCN layers: ha -> hb -> ha -> xf (fp32)
    const int lblocks = (NN + 63) / 64;
    k_layer<true ><<<lblocks, 256>>>(ha, wh + 0 * DD * DD, gcn_b + 0 * DD, hb, nullptr);
    k_layer<true ><<<lblocks, 256>>>(hb, wh + 1 * DD * DD, gcn_b + 1 * DD, ha, nullptr);
    k_layer<false><<<lblocks, 256>>>(ha, wh + 2 * DD * DD, gcn_b + 2 * DD, nullptr, xf);

    // FC head
    k_fc<<<1563, 256>>>(fc_w, xf, out);
}

// round 12
// speedup vs baseline: 1.1287x; 1.1287x over previous
#include <cuda_runtime.h>
#include <cuda_fp16.h>
#include <mma.h>

using namespace nvcuda;

// Problem constants (GCN_48473000903499): N=50000, D=64, L=3, OUT=16, E=800000
#define NN   50000
#define DD   64
#define OUTK 16
#define EE   800000
#define NE   (EE + NN)            // edges + self loops = 850000
#define NEP  (NE + 7 * NN)        // CSR capacity with per-row pad-to-8
#define NM   (NN * DD)            // 3,200,000 flat elements
#define NH2  (NN * 32)            // half2 count of real rows
#define NH2P ((NN + 1) * 32)      // + one zero pad row (index NN)
#define LDS_PAD 72                // smem row stride (halves / floats)

// ---- scratch (device globals; no allocation allowed) ----
// g_ints: [0,NN) deg_out(edges), [NN,2NN) deg_in(edges)->padded row len, [2NN] alloc counter
__device__ int     g_ints[2 * NN + 1];
__device__ int     g_off[NN];
__device__ int     g_cursor[NN];
__device__ int     g_csr_src[NEP];
__device__ float   g_norm_src[NN];
__device__ float   g_norm_dst[NN];
__device__ __align__(16) __half2 g_ha[NH2P];   // fp16 feature ping (row NN = zeros)
__device__ __align__(16) __half2 g_hb[NH2P];   // fp16 feature pong (row NN = zeros)
__device__ __align__(16) __half  g_wh[3 * DD * DD];  // fp16-converted gcn_w
__device__ float   g_xf[NM];       // final-layer fp32 output (FC input)

__device__ __forceinline__ float2 h2f_bits(float w) {
    unsigned u = __float_as_uint(w);
    __half2 h = *reinterpret_cast<__half2*>(&u);
    return __half22float2(h);
}

// ---------------------------------------------------------------------------
// 1. histogram edges (deg arrays pre-zeroed by memset)
__global__ void k_hist(const int* __restrict__ src, const int* __restrict__ dst) {
    int e = blockIdx.x * blockDim.x + threadIdx.x;
    if (e < EE) {
        atomicAdd(&g_ints[src[e]], 1);          // deg_out
        atomicAdd(&g_ints[NN + dst[e]], 1);     // deg_in
    }
}

// 2. per-node: norms (+1 self loop), padded CSR slot alloc, pad-fill with zero-row
//    index NN, bias init, zero pad feature rows, and fp16-convert gcn_w (once).
__global__ void k_build(const float* __restrict__ fc_b, float* __restrict__ out,
                        const float* __restrict__ gcn_w) {
    int i = blockIdx.x * blockDim.x + threadIdx.x;
    if (i < NN) {
        int dout = g_ints[i] + 1;
        int din  = g_ints[NN + i] + 1;          // entries incl. self loop
        g_norm_src[i] = rsqrtf((float)dout);
        g_norm_dst[i] = rsqrtf((float)din);
        int dpad = (din + 7) & ~7;
        int off = atomicAdd(&g_ints[2 * NN], dpad);
        g_off[i] = off;
        g_cursor[i] = off;
        g_ints[NN + i] = dpad;                  // repurpose: padded row length
        for (int p = off + din; p < off + dpad; p++) g_csr_src[p] = NN;
    }
    if (blockIdx.x == 0) {
        if (threadIdx.x < OUTK) out[threadIdx.x] = fc_b[threadIdx.x];
        if (threadIdx.x >= 32 && threadIdx.x < 64) {   // zero pad rows
            int l = threadIdx.x - 32;
            g_ha[NN * 32 + l] = __floats2half2_rn(0.f, 0.f);
            g_hb[NN * 32 + l] = __floats2half2_rn(0.f, 0.f);
        }
    }
    // blocks 100..147: convert 3*64*64 = 12288 W entries to fp16
    if (blockIdx.x >= 100 && blockIdx.x < 148) {
        int wi = (blockIdx.x - 100) * 256 + threadIdx.x;
        g_wh[wi] = __float2half(gcn_w[wi]);
    }
}

// 3. fused: scatter edges+loops into CSR, and premul F*norm_src -> fp16 ha
__global__ void k_scatpre(const int* __restrict__ src, const int* __restrict__ dst,
                          const float* __restrict__ F) {
    int i = blockIdx.x * blockDim.x + threadIdx.x;
    if (i < NE) {
        if (i < EE) {
            int d = dst[i];
            int p = atomicAdd(&g_cursor[d], 1);
            g_csr_src[p] = src[i];
        } else {
            int n = i - EE;
            int p = atomicAdd(&g_cursor[n], 1);
            g_csr_src[p] = n;
        }
    } else {
        int j = i - NE;                         // half2 index
        if (j < NH2) {
            float2 f = ((const float2*)F)[j];
            float ns = g_norm_src[j >> 5];
            g_ha[j] = __floats2half2_rn(f.x * ns, f.y * ns);
        }
    }
}

// 4. fused SpMM gather + HMMA GEMM + bias + relu. 64 nodes per block, 8 warps.
//    Gather: 4 source rows per LDG.128 (8 lanes/row, 16B/lane); lane l owns
//    column-chunk (l&7) of row-group (l>>3); shfl_xor(16,8) folds row-groups.
//    v[8] staging: up to 8 LDG.128 in flight per 32-edge window (round-9 form —
//    per-warp bytes-in-flight beats occupancy for this L2-latency-bound gather).
struct SmemP1 { __half Wh[DD][LDS_PAD]; __half aggh[DD][LDS_PAD]; };
union  SmemU  { SmemP1 p1; float outS[DD][LDS_PAD]; };

template <bool HALF_OUT>
__global__ void __launch_bounds__(256) k_layer(
    const __half2* __restrict__ x2, const __half* __restrict__ Wh16,
    const float* __restrict__ b, __half2* __restrict__ yh, float* __restrict__ yf)
{
    __shared__ SmemU sm;
    __shared__ float bsh[DD];

    int tid = threadIdx.x;
    int warp = tid >> 5, lane = tid & 31;
    int nodeBase = blockIdx.x * 64;

    // W tile: fp16 copy, vectorized uint2 (8B) to respect 144B row stride
    {
        const uint2* ws = (const uint2*)Wh16;
        for (int i = tid; i < DD * DD / 4; i += 256) {
            uint2 u = ws[i];
            *(uint2*)&sm.p1.Wh[i >> 4][(i * 4) & 63] = u;
        }
    }
    if (tid < DD) bsh[tid] = b[tid];

    // lane-parallel preload of this warp's 8 row offsets / padded lengths
    int group = nodeBase + warp * 8;
    int offv = 0, lenv = 0;
    if (lane < 8 && group + lane < NN) {
        offv = g_off[group + lane];
        lenv = g_ints[NN + group + lane];
    }
    __syncthreads();

    // ---- Phase A: gather (4 rows per LDG.128) ----
    const float4* xr = (const float4*)x2;      // row = 8 float4s (128 B)
    int rowgrp = lane >> 3;                    // 0..3
    int chunk  = lane & 7;                     // 16B column chunk
    #pragma unroll 1
    for (int it = 0; it < 8; it++) {
        int s0  = __shfl_sync(0xffffffffu, offv, it);
        int len = __shfl_sync(0xffffffffu, lenv, it);   // multiple of 8 (0 if OOB)
        float2 a0 = {0.f, 0.f}, a1 = {0.f, 0.f}, a2 = {0.f, 0.f}, a3 = {0.f, 0.f};

        #pragma unroll 1
        for (int base = 0; base < len; base += 32) {
            int rem = len - base;
            int s = (lane < rem) ? g_csr_src[s0 + base + lane] : NN;
            int nb = (rem < 32 ? rem : 32) >> 2;        // 2,4,6,8 batches of 4 rows
            float4 v[8];
            #pragma unroll
            for (int q = 0; q < 8; q++) {
                int ss = __shfl_sync(0xffffffffu, s, q * 4 + rowgrp);
                if (q < nb) v[q] = __ldg(&xr[ss * 8 + chunk]);
            }
            #pragma unroll
            for (int q = 0; q < 8; q++) {
                if (q < nb) {
                    float4 f = v[q];
                    float2 f0 = h2f_bits(f.x), f1 = h2f_bits(f.y);
                    float2 f2 = h2f_bits(f.z), f3 = h2f_bits(f.w);
                    a0.x += f0.x; a0.y += f0.y;
                    a1.x += f1.x; a1.y += f1.y;
                    a2.x += f2.x; a2.y += f2.y;
                    a3.x += f3.x; a3.y += f3.y;
                }
            }
        }
        // fold the 4 row-group partials (lanes c, c+8, c+16, c+24)
        #pragma unroll
        for (int st = 16; st >= 8; st >>= 1) {
            a0.x += __shfl_xor_sync(0xffffffffu, a0.x, st);
            a0.y += __shfl_xor_sync(0xffffffffu, a0.y, st);
            a1.x += __shfl_xor_sync(0xffffffffu, a1.x, st);
            a1.y += __shfl_xor_sync(0xffffffffu, a1.y, st);
            a2.x += __shfl_xor_sync(0xffffffffu, a2.x, st);
            a2.y += __shfl_xor_sync(0xffffffffu, a2.y, st);
            a3.x += __shfl_xor_sync(0xffffffffu, a3.x, st);
            a3.y += __shfl_xor_sync(0xffffffffu, a3.y, st);
        }
        int node = group + it;
        if (rowgrp == 0 && node < NN) {
            float nd = g_norm_dst[node];
            int local = warp * 8 + it;
            __half2* dp = (__half2*)&sm.p1.aggh[local][chunk * 8];
            dp[0] = __floats2half2_rn(a0.x * nd, a0.y * nd);
            dp[1] = __floats2half2_rn(a1.x * nd, a1.y * nd);
            dp[2] = __floats2half2_rn(a2.x * nd, a2.y * nd);
            dp[3] = __floats2half2_rn(a3.x * nd, a3.y * nd);
        }
    }
    __syncthreads();

    // ---- Phase B: 64x64x64 GEMM via HMMA (C kept in regs across barrier) ----
    int mi = warp >> 1;                // m-strip 0..3 (16 rows each)
    int n0 = (warp & 1) * 2;           // n-tile pair: tiles n0, n0+1

    wmma::fragment<wmma::accumulator, 16, 16, 16, float> cF0, cF1;
    wmma::fill_fragment(cF0, 0.f);
    wmma::fill_fragment(cF1, 0.f);
    #pragma unroll
    for (int k = 0; k < 4; k++) {
        wmma::fragment<wmma::matrix_a, 16, 16, 16, __half, wmma::row_major> aF;
        wmma::load_matrix_sync(aF, &sm.p1.aggh[mi * 16][k * 16], LDS_PAD);
        wmma::fragment<wmma::matrix_b, 16, 16, 16, __half, wmma::row_major> bF;
        wmma::load_matrix_sync(bF, &sm.p1.Wh[k * 16][n0 * 16], LDS_PAD);
        wmma::mma_sync(cF0, aF, bF, cF0);
        wmma::load_matrix_sync(bF, &sm.p1.Wh[k * 16][(n0 + 1) * 16], LDS_PAD);
        wmma::mma_sync(cF1, aF, bF, cF1);
    }
    __syncthreads();    // everyone done reading Wh/aggh; smem now becomes outS
    wmma::store_matrix_sync(&sm.outS[mi * 16][n0 * 16], cF0, LDS_PAD,
                            wmma::mem_row_major);
    wmma::store_matrix_sync(&sm.outS[mi * 16][(n0 + 1) * 16], cF1, LDS_PAD,
                            wmma::mem_row_major);
    __syncthreads();

    // ---- Phase C: epilogue ----
    int c0 = lane * 2;
    #pragma unroll 1
    for (int r = warp * 8; r < warp * 8 + 8; r++) {
        int node = nodeBase + r;
        if (node >= NN) break;
        float o0 = fmaxf(sm.outS[r][c0]     + bsh[c0],     0.f);
        float o1 = fmaxf(sm.outS[r][c0 + 1] + bsh[c0 + 1], 0.f);
        if (HALF_OUT) {
            float ns = g_norm_src[node];
            yh[node * 32 + lane] = __floats2half2_rn(o0 * ns, o1 * ns);
        } else {
            *(float2*)&yf[node * DD + c0] = make_float2(o0, o1);
        }
    }
}

// 5. out += fc_w @ relu(flat)   (DRAM-streaming GEMV; fc_w streamed evict-first)
__global__ void __launch_bounds__(256) k_fc(
    const float* __restrict__ fc_w, const float* __restrict__ xflat,
    float* __restrict__ out)
{
    __shared__ float sh[OUTK];
    if (threadIdx.x < OUTK) sh[threadIdx.x] = 0.f;
    __syncthreads();

    const int nv = NM / 4;  // 800000 float4s per output row
    float acc[OUTK];
    #pragma unroll
    for (int o = 0; o < OUTK; o++) acc[o] = 0.f;

    const float4* w4 = (const float4*)fc_w;
    const float4* x4 = (const float4*)xflat;
    int stride = gridDim.x * blockDim.x;
    for (int i = blockIdx.x * blockDim.x + threadIdx.x; i < nv; i += stride) {
        float4 f = x4[i];
        f.x = fmaxf(f.x, 0.f); f.y = fmaxf(f.y, 0.f);
        f.z = fmaxf(f.z, 0.f); f.w = fmaxf(f.w, 0.f);
        #pragma unroll
        for (int o = 0; o < OUTK; o++) {
            float4 w = __ldcs(&w4[(size_t)o * nv + i]);
            acc[o] = fmaf(w.x, f.x, acc[o]);
            acc[o] = fmaf(w.y, f.y, acc[o]);
            acc[o] = fmaf(w.z, f.z, acc[o]);
            acc[o] = fmaf(w.w, f.w, acc[o]);
        }
    }

    #pragma unroll
    for (int o = 0; o < OUTK; o++) {
        float v = acc[o];
        #pragma unroll
        for (int s = 16; s; s >>= 1) v += __shfl_xor_sync(0xffffffffu, v, s);
        if ((threadIdx.x & 31) == 0) atomicAdd(&sh[o], v);
    }
    __syncthreads();
    if (threadIdx.x < OUTK) atomicAdd(&out[threadIdx.x], sh[threadIdx.x]);
}

// ---------------------------------------------------------------------------
extern "C" void kernel_launch(void* const* d_in, const int* in_sizes, int n_in,
                              void* d_out, int out_size)
{
    const float* F     = (const float*)d_in[0];
    const int*   src   = (const int*)d_in[1];
    const int*   dst   = (const int*)d_in[2];
    const float* gcn_w = (const float*)d_in[3];
    const float* gcn_b = (const float*)d_in[4];
    const float* fc_w  = (const float*)d_in[5];
    const float* fc_b  = (const float*)d_in[6];
    float* out = (float*)d_out;

    void* ints_addr;   cudaGetSymbolAddress(&ints_addr, g_ints);
    __half2* ha; cudaGetSymbolAddress((void**)&ha, g_ha);
    __half2* hb; cudaGetSymbolAddress((void**)&hb, g_hb);
    __half*  wh; cudaGetSymbolAddress((void**)&wh, g_wh);
    float*   xf; cudaGetSymbolAddress((void**)&xf, g_xf);

    // graph prep
    cudaMemsetAsync(ints_addr, 0, (2 * NN + 1) * sizeof(int));
    k_hist<<<(EE + 255) / 256, 256>>>(src, dst);
    k_build<<<(NN + 255) / 256, 256>>>(fc_b, out, gcn_w);
    k_scatpre<<<(NE + NH2 + 255) / 256, 256>>>(src, dst, F);

    // 3 GCN layers: ha -> hb -> ha -> xf (fp32)
    const int lblocks = (NN + 63) / 64;
    k_layer<true ><<<lblocks, 256>>>(ha, wh + 0 * DD * DD, gcn_b + 0 * DD, hb, nullptr);
    k_layer<true ><<<lblocks, 256>>>(hb, wh + 1 * DD * DD, gcn_b + 1 * DD, ha, nullptr);
    k_layer<false><<<lblocks, 256>>>(ha, wh + 2 * DD * DD, gcn_b + 2 * DD, nullptr, xf);

    // FC head
    k_fc<<<1563, 256>>>(fc_w, xf, out);
}